// round 1
// baseline (speedup 1.0000x reference)
#include <cuda_runtime.h>
#include <cuda_bf16.h>
#include <mma.h>
#include <cstdint>
#include <cstddef>

using namespace nvcuda;

// ---------------- problem constants ----------------
#define T_TOK   4112
#define DIMC    2048
#define NHEAD   16
#define HDIM    128
#define BSZ     16
#define NPSEQ_C 2
#define PLEN_C  2048
#define NPTOK_C 4096
#define ND_C    16
#define MB_C    129
#define QKV_LD  6144
#define ATTN_SCALE 0.08838834764831845f  // 1/sqrt(128)

// ---------------- scratch (device globals; no runtime alloc) ----------------
__device__ float g_hnorm[(size_t)T_TOK * DIMC];
__device__ float g_qkv  [(size_t)T_TOK * 3 * DIMC];
__device__ float g_attn [(size_t)T_TOK * DIMC];
__device__ float g_h2   [(size_t)T_TOK * DIMC];
__device__ float g_act  [(size_t)T_TOK * 4 * DIMC];

// ---------------- rmsnorm ----------------
__global__ void __launch_bounds__(256) rmsnorm_k(const float* __restrict__ x,
                                                 const float* __restrict__ w,
                                                 float* __restrict__ out)
{
    const int row = blockIdx.x;
    const int tid = threadIdx.x;
    const float4* xr = (const float4*)(x + (size_t)row * DIMC);
    float4 v0 = xr[tid];
    float4 v1 = xr[tid + 256];
    float ss = v0.x*v0.x + v0.y*v0.y + v0.z*v0.z + v0.w*v0.w
             + v1.x*v1.x + v1.y*v1.y + v1.z*v1.z + v1.w*v1.w;
#pragma unroll
    for (int off = 16; off; off >>= 1) ss += __shfl_xor_sync(0xffffffffu, ss, off);
    __shared__ float red[8];
    if ((tid & 31) == 0) red[tid >> 5] = ss;
    __syncthreads();
    float tot = red[0] + red[1] + red[2] + red[3] + red[4] + red[5] + red[6] + red[7];
    float inv = rsqrtf(tot * (1.0f / 2048.0f) + 1e-5f);
    const float4* wr = (const float4*)w;
    float4 w0 = wr[tid], w1 = wr[tid + 256];
    float4* orow = (float4*)(out + (size_t)row * DIMC);
    float4 o0, o1;
    o0.x = v0.x * inv * w0.x; o0.y = v0.y * inv * w0.y;
    o0.z = v0.z * inv * w0.z; o0.w = v0.w * inv * w0.w;
    o1.x = v1.x * inv * w1.x; o1.y = v1.y * inv * w1.y;
    o1.z = v1.z * inv * w1.z; o1.w = v1.w * inv * w1.w;
    orow[tid]       = o0;
    orow[tid + 256] = o1;
}

// ---------------- generic tf32 GEMM: C = A(MxK) * B(KxN) [+ R] ----------------
// BM=128 BN=128 BK=32, 8 warps (4x2), warp tile 32x64, wmma 16x16x8 tf32.
#define GA_LD 40
#define GB_LD 136
#define GC_LD 136
#define GEMM_SMEM_BYTES (128 * GC_LD * 4)   // 69632 (>= load-phase 9472 floats)

template<int EPI>
__global__ void __launch_bounds__(256) gemm_tf32_k(const float* __restrict__ A,
                                                   const float* __restrict__ B,
                                                   const float* __restrict__ R,
                                                   float* __restrict__ C,
                                                   int M, int N, int K)
{
    extern __shared__ float sm[];
    float* As = sm;                 // 128 x GA_LD
    float* Bs = sm + 128 * GA_LD;   // 32  x GB_LD
    const int tid = threadIdx.x;
    const int wid = tid >> 5;
    const int wm = wid >> 1, wn = wid & 1;
    const int bm = blockIdx.y * 128, bn = blockIdx.x * 128;

    wmma::fragment<wmma::accumulator, 16, 16, 8, float> acc[2][4];
#pragma unroll
    for (int i = 0; i < 2; i++)
#pragma unroll
        for (int j = 0; j < 4; j++) wmma::fill_fragment(acc[i][j], 0.0f);

    for (int k0 = 0; k0 < K; k0 += 32) {
#pragma unroll
        for (int p = 0; p < 4; p++) {            // A tile: 128x32
            int idx = p * 256 + tid;
            int r = idx >> 3;
            int c = (idx & 7) << 2;
            float4 v = make_float4(0.f, 0.f, 0.f, 0.f);
            if (bm + r < M) v = *(const float4*)(A + (size_t)(bm + r) * K + k0 + c);
            float* dst = As + r * GA_LD + c;
            dst[0] = wmma::__float_to_tf32(v.x);
            dst[1] = wmma::__float_to_tf32(v.y);
            dst[2] = wmma::__float_to_tf32(v.z);
            dst[3] = wmma::__float_to_tf32(v.w);
        }
#pragma unroll
        for (int p = 0; p < 4; p++) {            // B tile: 32x128
            int idx = p * 256 + tid;
            int r = idx >> 5;
            int c = (idx & 31) << 2;
            float4 v = *(const float4*)(B + (size_t)(k0 + r) * N + bn + c);
            float* dst = Bs + r * GB_LD + c;
            dst[0] = wmma::__float_to_tf32(v.x);
            dst[1] = wmma::__float_to_tf32(v.y);
            dst[2] = wmma::__float_to_tf32(v.z);
            dst[3] = wmma::__float_to_tf32(v.w);
        }
        __syncthreads();
#pragma unroll
        for (int ks = 0; ks < 32; ks += 8) {
            wmma::fragment<wmma::matrix_a, 16, 16, 8, wmma::precision::tf32, wmma::row_major> af[2];
            wmma::fragment<wmma::matrix_b, 16, 16, 8, wmma::precision::tf32, wmma::row_major> bf[4];
#pragma unroll
            for (int i = 0; i < 2; i++)
                wmma::load_matrix_sync(af[i], As + (wm * 32 + i * 16) * GA_LD + ks, GA_LD);
#pragma unroll
            for (int j = 0; j < 4; j++)
                wmma::load_matrix_sync(bf[j], Bs + ks * GB_LD + wn * 64 + j * 16, GB_LD);
#pragma unroll
            for (int i = 0; i < 2; i++)
#pragma unroll
                for (int j = 0; j < 4; j++)
                    wmma::mma_sync(acc[i][j], af[i], bf[j], acc[i][j]);
        }
        __syncthreads();
    }
    // epilogue via smem staging (handles M edge + residual)
    float* Cs = sm;   // 128 x GC_LD
#pragma unroll
    for (int i = 0; i < 2; i++)
#pragma unroll
        for (int j = 0; j < 4; j++)
            wmma::store_matrix_sync(Cs + (wm * 32 + i * 16) * GC_LD + wn * 64 + j * 16,
                                    acc[i][j], GC_LD, wmma::mem_row_major);
    __syncthreads();
#pragma unroll
    for (int p = 0; p < 16; p++) {
        int idx = p * 256 + tid;
        int r = idx >> 5;
        int c = (idx & 31) << 2;
        if (bm + r < M) {
            float4 v = *(const float4*)(Cs + r * GC_LD + c);
            if (EPI == 1) {
                float4 rv = *(const float4*)(R + (size_t)(bm + r) * N + bn + c);
                v.x += rv.x; v.y += rv.y; v.z += rv.z; v.w += rv.w;
            }
            *(float4*)(C + (size_t)(bm + r) * N + bn + c) = v;
        }
    }
}

// ---------------- fused gate_up GEMM + SiLU ----------------
// C tile 128 x 64; computes gate (cols bn..bn+63) and up (cols 8192+bn..) together.
#define GU_LD 72
#define GATEUP_SMEM_BYTES (2 * 128 * GU_LD * 4)   // 73728 (>= load-phase 9728 floats)

__global__ void __launch_bounds__(256) gateup_silu_k(const float* __restrict__ A,
                                                     const float* __restrict__ B,
                                                     float* __restrict__ ACT, int M)
{
    extern __shared__ float sm[];
    float* As = sm;                    // 128 x GA_LD
    float* Bg = sm + 128 * GA_LD;      // 32 x GU_LD
    float* Bu = Bg + 32 * GU_LD;       // 32 x GU_LD
    const int tid = threadIdx.x;
    const int wid = tid >> 5;
    const int wm = wid >> 1, wn = wid & 1;
    const int bm = blockIdx.y * 128, bn = blockIdx.x * 64;
    const int K = 2048, NB = 16384;

    wmma::fragment<wmma::accumulator, 16, 16, 8, float> accg[2][2], accu[2][2];
#pragma unroll
    for (int i = 0; i < 2; i++)
#pragma unroll
        for (int j = 0; j < 2; j++) {
            wmma::fill_fragment(accg[i][j], 0.0f);
            wmma::fill_fragment(accu[i][j], 0.0f);
        }

    for (int k0 = 0; k0 < K; k0 += 32) {
#pragma unroll
        for (int p = 0; p < 4; p++) {            // A tile 128x32
            int idx = p * 256 + tid;
            int r = idx >> 3;
            int c = (idx & 7) << 2;
            float4 v = make_float4(0.f, 0.f, 0.f, 0.f);
            if (bm + r < M) v = *(const float4*)(A + (size_t)(bm + r) * K + k0 + c);
            float* dst = As + r * GA_LD + c;
            dst[0] = wmma::__float_to_tf32(v.x);
            dst[1] = wmma::__float_to_tf32(v.y);
            dst[2] = wmma::__float_to_tf32(v.z);
            dst[3] = wmma::__float_to_tf32(v.w);
        }
#pragma unroll
        for (int p = 0; p < 2; p++) {            // B tiles 32x64 (gate & up)
            int idx = p * 256 + tid;
            int r = idx >> 4;
            int c = (idx & 15) << 2;
            const float* srcg = B + (size_t)(k0 + r) * NB + bn + c;
            float4 vg = *(const float4*)srcg;
            float4 vu = *(const float4*)(srcg + 8192);
            float* dg = Bg + r * GU_LD + c;
            float* du = Bu + r * GU_LD + c;
            dg[0] = wmma::__float_to_tf32(vg.x); dg[1] = wmma::__float_to_tf32(vg.y);
            dg[2] = wmma::__float_to_tf32(vg.z); dg[3] = wmma::__float_to_tf32(vg.w);
            du[0] = wmma::__float_to_tf32(vu.x); du[1] = wmma::__float_to_tf32(vu.y);
            du[2] = wmma::__float_to_tf32(vu.z); du[3] = wmma::__float_to_tf32(vu.w);
        }
        __syncthreads();
#pragma unroll
        for (int ks = 0; ks < 32; ks += 8) {
            wmma::fragment<wmma::matrix_a, 16, 16, 8, wmma::precision::tf32, wmma::row_major> af[2];
            wmma::fragment<wmma::matrix_b, 16, 16, 8, wmma::precision::tf32, wmma::row_major> bgf[2], buf[2];
#pragma unroll
            for (int i = 0; i < 2; i++)
                wmma::load_matrix_sync(af[i], As + (wm * 32 + i * 16) * GA_LD + ks, GA_LD);
#pragma unroll
            for (int j = 0; j < 2; j++) {
                wmma::load_matrix_sync(bgf[j], Bg + ks * GU_LD + wn * 32 + j * 16, GU_LD);
                wmma::load_matrix_sync(buf[j], Bu + ks * GU_LD + wn * 32 + j * 16, GU_LD);
            }
#pragma unroll
            for (int i = 0; i < 2; i++)
#pragma unroll
                for (int j = 0; j < 2; j++) {
                    wmma::mma_sync(accg[i][j], af[i], bgf[j], accg[i][j]);
                    wmma::mma_sync(accu[i][j], af[i], buf[j], accu[i][j]);
                }
        }
        __syncthreads();
    }
    float* Gs = sm;                 // 128 x GU_LD
    float* Us = sm + 128 * GU_LD;   // 128 x GU_LD
#pragma unroll
    for (int i = 0; i < 2; i++)
#pragma unroll
        for (int j = 0; j < 2; j++) {
            wmma::store_matrix_sync(Gs + (wm * 32 + i * 16) * GU_LD + wn * 32 + j * 16,
                                    accg[i][j], GU_LD, wmma::mem_row_major);
            wmma::store_matrix_sync(Us + (wm * 32 + i * 16) * GU_LD + wn * 32 + j * 16,
                                    accu[i][j], GU_LD, wmma::mem_row_major);
        }
    __syncthreads();
#pragma unroll
    for (int p = 0; p < 8; p++) {
        int idx = p * 256 + tid;
        int r = idx >> 4;
        int c = (idx & 15) << 2;
        if (bm + r < M) {
            float4 gv = *(const float4*)(Gs + r * GU_LD + c);
            float4 uv = *(const float4*)(Us + r * GU_LD + c);
            float4 o;
            o.x = gv.x / (1.f + __expf(-gv.x)) * uv.x;
            o.y = gv.y / (1.f + __expf(-gv.y)) * uv.y;
            o.z = gv.z / (1.f + __expf(-gv.z)) * uv.z;
            o.w = gv.w / (1.f + __expf(-gv.w)) * uv.w;
            *(float4*)(ACT + (size_t)(bm + r) * 8192 + bn + c) = o;
        }
    }
}

// ---------------- prefill flash attention (fp32 SIMT) ----------------
// block: (qtile 64) x head x seq; 256 threads; thread (r=tid/4, c=tid%4)
#define QLD 132
#define PLD 68
#define PREFILL_SMEM_BYTES ((3 * 64 * QLD + 64 * PLD) * 4)  // 118784

__global__ void __launch_bounds__(256) prefill_attn_k(const float* __restrict__ qkv,
                                                      float* __restrict__ attn)
{
    extern __shared__ float sm[];
    float* Qs = sm;
    float* Ks = Qs + 64 * QLD;
    float* Vs = Ks + 64 * QLD;
    float* Ps = Vs + 64 * QLD;
    const int tid = threadIdx.x;
    const int qt = blockIdx.x, h = blockIdx.y, b = blockIdx.z;
    const int q0 = qt * 64;

#pragma unroll
    for (int p = 0; p < 8; p++) {            // Q tile 64x128
        int idx = p * 256 + tid;
        int r = idx >> 5;
        int c = (idx & 31) << 2;
        *(float4*)(Qs + r * QLD + c) =
            *(const float4*)(qkv + (size_t)(b * PLEN_C + q0 + r) * QKV_LD + h * HDIM + c);
    }

    const int r = tid >> 2, c = tid & 3;
    float m = -INFINITY, l = 0.f;
    float o[32];
#pragma unroll
    for (int j = 0; j < 32; j++) o[j] = 0.f;

    for (int kt = 0; kt <= qt; kt++) {
        const int k0 = kt * 64;
#pragma unroll
        for (int p = 0; p < 8; p++) {        // K and V tiles 64x128
            int idx = p * 256 + tid;
            int rr = idx >> 5;
            int cc = (idx & 31) << 2;
            const float* base = qkv + (size_t)(b * PLEN_C + k0 + rr) * QKV_LD + h * HDIM + cc;
            *(float4*)(Ks + rr * QLD + cc) = *(const float4*)(base + 2048);
            *(float4*)(Vs + rr * QLD + cc) = *(const float4*)(base + 4096);
        }
        __syncthreads();

        float s[16];
#pragma unroll
        for (int kk = 0; kk < 16; kk++) s[kk] = 0.f;
#pragma unroll 4
        for (int d4 = 0; d4 < 32; d4++) {
            float4 q4 = *(const float4*)(Qs + r * QLD + d4 * 4);
#pragma unroll
            for (int kk = 0; kk < 16; kk++) {
                float4 k4 = *(const float4*)(Ks + (kk * 4 + c) * QLD + d4 * 4);
                s[kk] += q4.x * k4.x + q4.y * k4.y + q4.z * k4.z + q4.w * k4.w;
            }
        }
        const bool diag = (kt == qt);
        float mx = -INFINITY;
#pragma unroll
        for (int kk = 0; kk < 16; kk++) {
            float sv = s[kk] * ATTN_SCALE;
            if (diag && (kk * 4 + c) > r) sv = -INFINITY;
            s[kk] = sv;
            mx = fmaxf(mx, sv);
        }
        mx = fmaxf(mx, __shfl_xor_sync(0xffffffffu, mx, 1));
        mx = fmaxf(mx, __shfl_xor_sync(0xffffffffu, mx, 2));
        float mnew = fmaxf(m, mx);
        float corr = __expf(m - mnew);
        float psum = 0.f;
#pragma unroll
        for (int kk = 0; kk < 16; kk++) {
            float pv = __expf(s[kk] - mnew);
            Ps[r * PLD + kk * 4 + c] = pv;
            psum += pv;
        }
        psum += __shfl_xor_sync(0xffffffffu, psum, 1);
        psum += __shfl_xor_sync(0xffffffffu, psum, 2);
        l = l * corr + psum;
        m = mnew;
#pragma unroll
        for (int j = 0; j < 32; j++) o[j] *= corr;
        __syncwarp();
#pragma unroll 4
        for (int k = 0; k < 64; k++) {
            float pv = Ps[r * PLD + k];
            const float4* vr = (const float4*)(Vs + k * QLD + c * 32);
#pragma unroll
            for (int j4 = 0; j4 < 8; j4++) {
                float4 v4 = vr[j4];
                o[j4 * 4 + 0] += pv * v4.x;
                o[j4 * 4 + 1] += pv * v4.y;
                o[j4 * 4 + 2] += pv * v4.z;
                o[j4 * 4 + 3] += pv * v4.w;
            }
        }
        __syncthreads();
    }
    const float invl = 1.f / l;
    float* dst = attn + (size_t)(b * PLEN_C + q0 + r) * DIMC + h * HDIM + c * 32;
#pragma unroll
    for (int j4 = 0; j4 < 8; j4++) {
        float4 v;
        v.x = o[j4 * 4 + 0] * invl;
        v.y = o[j4 * 4 + 1] * invl;
        v.z = o[j4 * 4 + 2] * invl;
        v.w = o[j4 * 4 + 3] * invl;
        ((float4*)dst)[j4] = v;
    }
}

// ---------------- decode attention ----------------
// One block per (decode token, head). History from heaps; fresh k/v at s==len-1.
__global__ void __launch_bounds__(256) decode_attn_k(const float* __restrict__ qkv,
                                                     const float* __restrict__ kheap,
                                                     const float* __restrict__ vheap,
                                                     const int* __restrict__ bt,
                                                     const int* __restrict__ lens,
                                                     float* __restrict__ attn)
{
    __shared__ float sc[2080];
    __shared__ float qs[128];
    __shared__ float red[8];
    __shared__ float obuf[128];
    const int i = blockIdx.x, h = blockIdx.y;
    const int tid = threadIdx.x, w = tid >> 5, lane = tid & 31;
    const int len = lens[i];
    const int trow = NPTOK_C + i;
    const float* qp = qkv + (size_t)trow * QKV_LD + h * HDIM;
    if (tid < 128) qs[tid] = qp[tid];
    __syncthreads();
    float4 qv = ((const float4*)qs)[lane];
    for (int s = w; s < len; s += 8) {
        const float* kp;
        if (s == len - 1) kp = qkv + (size_t)trow * QKV_LD + 2048 + h * HDIM;
        else {
            int blk = bt[i * MB_C + (s >> 4)];
            kp = kheap + (((size_t)blk * BSZ + (s & 15)) * NHEAD + h) * HDIM;
        }
        float4 k4 = ((const float4*)kp)[lane];
        float a = qv.x * k4.x + qv.y * k4.y + qv.z * k4.z + qv.w * k4.w;
#pragma unroll
        for (int off = 16; off; off >>= 1) a += __shfl_xor_sync(0xffffffffu, a, off);
        if (lane == 0) sc[s] = a * ATTN_SCALE;
    }
    __syncthreads();
    float mx = -INFINITY;
    for (int s = tid; s < len; s += 256) mx = fmaxf(mx, sc[s]);
#pragma unroll
    for (int off = 16; off; off >>= 1) mx = fmaxf(mx, __shfl_xor_sync(0xffffffffu, mx, off));
    if (lane == 0) red[w] = mx;
    __syncthreads();
    float bmax = red[0];
#pragma unroll
    for (int j = 1; j < 8; j++) bmax = fmaxf(bmax, red[j]);
    __syncthreads();
    float sum = 0.f;
    for (int s = tid; s < len; s += 256) {
        float e = __expf(sc[s] - bmax);
        sc[s] = e;
        sum += e;
    }
#pragma unroll
    for (int off = 16; off; off >>= 1) sum += __shfl_xor_sync(0xffffffffu, sum, off);
    if (lane == 0) red[w] = sum;
    __syncthreads();
    float bsum = red[0] + red[1] + red[2] + red[3] + red[4] + red[5] + red[6] + red[7];
    const int d = tid & 127, half = tid >> 7;
    float o = 0.f;
    for (int s = half; s < len; s += 2) {
        const float* vp;
        if (s == len - 1) vp = qkv + (size_t)trow * QKV_LD + 4096 + h * HDIM;
        else {
            int blk = bt[i * MB_C + (s >> 4)];
            vp = vheap + (((size_t)blk * BSZ + (s & 15)) * NHEAD + h) * HDIM;
        }
        o += sc[s] * vp[d];
    }
    if (half) obuf[d] = o;
    __syncthreads();
    if (!half) attn[(size_t)trow * DIMC + h * HDIM + d] = (o + obuf[d]) / bsum;
}

// ---------------- launch ----------------
extern "C" void kernel_launch(void* const* d_in, const int* in_sizes, int n_in,
                              void* d_out, int out_size)
{
    const float* x     = (const float*)d_in[0];
    const float* kheap = (const float*)d_in[1];
    const float* vheap = (const float*)d_in[2];
    // d_in[3] slot_mapping: unused (scatter is dead work; decode substitutes fresh kv)
    const int*   bt    = (const int*)d_in[4];
    const int*   lens  = (const int*)d_in[5];
    const float* w_qkv = (const float*)d_in[6];
    const float* wo    = (const float*)d_in[7];
    const float* wgu   = (const float*)d_in[8];
    const float* w2    = (const float*)d_in[9];
    const float* n1    = (const float*)d_in[10];
    const float* n2    = (const float*)d_in[11];
    float* out = (float*)d_out;
    (void)in_sizes; (void)n_in; (void)out_size;

    float *hnorm, *qkv, *attn, *h2, *act;
    cudaGetSymbolAddress((void**)&hnorm, g_hnorm);
    cudaGetSymbolAddress((void**)&qkv,   g_qkv);
    cudaGetSymbolAddress((void**)&attn,  g_attn);
    cudaGetSymbolAddress((void**)&h2,    g_h2);
    cudaGetSymbolAddress((void**)&act,   g_act);

    cudaFuncSetAttribute(gemm_tf32_k<0>, cudaFuncAttributeMaxDynamicSharedMemorySize, GEMM_SMEM_BYTES);
    cudaFuncSetAttribute(gemm_tf32_k<1>, cudaFuncAttributeMaxDynamicSharedMemorySize, GEMM_SMEM_BYTES);
    cudaFuncSetAttribute(gateup_silu_k,  cudaFuncAttributeMaxDynamicSharedMemorySize, GATEUP_SMEM_BYTES);
    cudaFuncSetAttribute(prefill_attn_k, cudaFuncAttributeMaxDynamicSharedMemorySize, PREFILL_SMEM_BYTES);

    // 1) h = rmsnorm(x)
    rmsnorm_k<<<T_TOK, 256>>>(x, n1, hnorm);
    // 2) qkv = h @ w_qkv
    gemm_tf32_k<0><<<dim3(6144 / 128, 33), 256, GEMM_SMEM_BYTES>>>(hnorm, w_qkv, nullptr, qkv,
                                                                   T_TOK, 6144, 2048);
    // 3) prefill attention (causal flash)
    prefill_attn_k<<<dim3(PLEN_C / 64, NHEAD, NPSEQ_C), 256, PREFILL_SMEM_BYTES>>>(qkv, attn);
    // 4) decode attention
    decode_attn_k<<<dim3(ND_C, NHEAD), 256>>>(qkv, kheap, vheap, bt, lens, attn);
    // 5) h2 = attn @ wo + x
    gemm_tf32_k<1><<<dim3(2048 / 128, 33), 256, GEMM_SMEM_BYTES>>>(attn, wo, x, h2,
                                                                   T_TOK, 2048, 2048);
    // 6) hnorm = rmsnorm(h2)
    rmsnorm_k<<<T_TOK, 256>>>(h2, n2, hnorm);
    // 7) act = silu(hnorm @ Wg) * (hnorm @ Wu)
    gateup_silu_k<<<dim3(8192 / 64, 33), 256, GATEUP_SMEM_BYTES>>>(hnorm, wgu, act, T_TOK);
    // 8) out = act @ w2 + h2
    gemm_tf32_k<1><<<dim3(2048 / 128, 33), 256, GEMM_SMEM_BYTES>>>(act, w2, h2, out,
                                                                   T_TOK, 2048, 8192);
}